// round 4
// baseline (speedup 1.0000x reference)
#include <cuda_runtime.h>
#include <cstdint>
#include <cstddef>

// ============================================================================
// TensorFusion: out = tanh(tanh(tanh(fusion@W1+b1)@W2+b2)@W3+b3)
// fusion[b, (i,j,k)] = a_h[b,i] * v_h[b,j] * t_h[b,k], each 65-dim ([1, x]).
//
// Kernel 1: out1[b,h] partial sums over i:
//   for each (i, mtile): C[b,h] = sum_j s_j[b] * (sum_k t_h[b,k] * W1[(i,j,k),h])
//   with s_j[b] = a_h[b,i] * v_h[b,j].
// Kernel 2: reduce 65 partials, bias+tanh, two 64x64 layers.
// ============================================================================

#define DL 64
#define DH 65            // DL + 1
#define HID 64
#define BATCH 512
#define MTILE 64         // rows per CTA
#define NMT (BATCH / MTILE)   // 8 M-tiles
#define THREADS 128

// Deterministic partial accumulator: [65][512][64] fp32 = 8.52 MB
__device__ float g_partials[(size_t)DH * BATCH * HID];

// ---- packed f32x2 helpers (Blackwell) --------------------------------------
__device__ __forceinline__ unsigned long long pack2(float lo, float hi) {
    unsigned long long r;
    asm("mov.b64 %0, {%1, %2};" : "=l"(r) : "f"(lo), "f"(hi));
    return r;
}
__device__ __forceinline__ void unpack2(unsigned long long v, float &lo, float &hi) {
    asm("mov.b64 {%0, %1}, %2;" : "=f"(lo), "=f"(hi) : "l"(v));
}
// d = a*b + d   (two fp32 FMAs in one instruction)
__device__ __forceinline__ void fma2(unsigned long long &d,
                                     unsigned long long a,
                                     unsigned long long b) {
    asm("fma.rn.f32x2 %0, %1, %2, %0;" : "+l"(d) : "l"(a), "l"(b));
}

// ============================================================================
// Kernel 1: main contraction.
// grid = (8 mtiles, 65 i-values), block = 128 threads.
// Thread micro-tile: 8 rows x 4 cols. Rows packed in pairs for f32x2.
// smem: Tsm[65][64] (k-major t_h tile), Wsm[65][64] (per-j W1 block), a_col[64]
// ============================================================================
__global__ void __launch_bounds__(THREADS, 4)
fusion_gemm_kernel(const float* __restrict__ l,
                   const float* __restrict__ a,
                   const float* __restrict__ v,
                   const float* __restrict__ W1)
{
    __shared__ float Tsm[DH][MTILE];   // [k][row]
    __shared__ float Wsm[DH][HID];     // [k][h]
    __shared__ float a_col[MTILE];

    const int tid = threadIdx.x;
    const int mt  = blockIdx.x;
    const int i   = blockIdx.y;
    const int b0  = mt * MTILE;

    const int tx = tid & 15;           // 16 col-groups
    const int ty = tid >> 4;           // 8 row-groups
    const int h0 = tx * 4;             // 4 cols
    const int r0 = ty * 8;             // 8 rows

    // ---- load t_h tile (k-major) and a-column ----
    for (int idx = tid; idx < DH * MTILE; idx += THREADS) {
        int k = idx >> 6;              // MTILE == 64
        int r = idx & 63;
        Tsm[k][r] = (k == 0) ? 1.0f : l[(size_t)(b0 + r) * DL + (k - 1)];
    }
    for (int r = tid; r < MTILE; r += THREADS) {
        a_col[r] = (i == 0) ? 1.0f : a[(size_t)(b0 + r) * DL + (i - 1)];
    }

    // ---- accumulators: 4 row-pairs x 4 cols, packed f32x2 ----
    unsigned long long C[4][4];
    #pragma unroll
    for (int p = 0; p < 4; ++p)
        #pragma unroll
        for (int c = 0; c < 4; ++c) C[p][c] = 0ull;

    for (int j = 0; j < DH; ++j) {
        __syncthreads();   // previous compute done before overwriting Wsm
        // load W1 block for (i, j): [65, 64] contiguous floats
        {
            const float4* src = reinterpret_cast<const float4*>(
                W1 + (size_t)(i * DH + j) * DH * HID);
            float4* dst = reinterpret_cast<float4*>(&Wsm[0][0]);
            #pragma unroll
            for (int idx = tid; idx < DH * HID / 4; idx += THREADS)
                dst[idx] = src[idx];
        }
        __syncthreads();

        // per-row scalar s = a_h[b,i] * v_h[b,j]
        float sv[8];
        #pragma unroll
        for (int q = 0; q < 8; ++q) {
            int b = b0 + r0 + q;
            float vh = (j == 0) ? 1.0f : v[(size_t)b * DL + (j - 1)];
            sv[q] = a_col[r0 + q] * vh;
        }

        // u[p][c] = sum_k t[row_pair][k] * w[k][col]
        unsigned long long u[4][4];
        #pragma unroll
        for (int p = 0; p < 4; ++p)
            #pragma unroll
            for (int c = 0; c < 4; ++c) u[p][c] = 0ull;

        #pragma unroll 13
        for (int k = 0; k < DH; ++k) {
            // 8 t-values = 4 packed row-pairs (16B-aligned LDS)
            ulonglong2 ta = *reinterpret_cast<const ulonglong2*>(&Tsm[k][r0]);
            ulonglong2 tb = *reinterpret_cast<const ulonglong2*>(&Tsm[k][r0 + 4]);
            float4 w = *reinterpret_cast<const float4*>(&Wsm[k][h0]);
            unsigned long long w0 = pack2(w.x, w.x);
            unsigned long long w1 = pack2(w.y, w.y);
            unsigned long long w2 = pack2(w.z, w.z);
            unsigned long long w3 = pack2(w.w, w.w);
            fma2(u[0][0], ta.x, w0); fma2(u[0][1], ta.x, w1);
            fma2(u[0][2], ta.x, w2); fma2(u[0][3], ta.x, w3);
            fma2(u[1][0], ta.y, w0); fma2(u[1][1], ta.y, w1);
            fma2(u[1][2], ta.y, w2); fma2(u[1][3], ta.y, w3);
            fma2(u[2][0], tb.x, w0); fma2(u[2][1], tb.x, w1);
            fma2(u[2][2], tb.x, w2); fma2(u[2][3], tb.x, w3);
            fma2(u[3][0], tb.y, w0); fma2(u[3][1], tb.y, w1);
            fma2(u[3][2], tb.y, w2); fma2(u[3][3], tb.y, w3);
        }

        // C += s * u  (scale-after-reduce: 1 extra FMA per 65)
        unsigned long long s2[4];
        #pragma unroll
        for (int p = 0; p < 4; ++p) s2[p] = pack2(sv[2 * p], sv[2 * p + 1]);
        #pragma unroll
        for (int p = 0; p < 4; ++p)
            #pragma unroll
            for (int c = 0; c < 4; ++c) fma2(C[p][c], u[p][c], s2[p]);
    }

    // ---- store partials[i][b][h] ----
    #pragma unroll
    for (int p = 0; p < 4; ++p) {
        float lo[4], hi[4];
        #pragma unroll
        for (int c = 0; c < 4; ++c) unpack2(C[p][c], lo[c], hi[c]);
        size_t row_e = (size_t)i * BATCH + b0 + r0 + 2 * p;
        *reinterpret_cast<float4*>(&g_partials[row_e * HID + h0]) =
            make_float4(lo[0], lo[1], lo[2], lo[3]);
        *reinterpret_cast<float4*>(&g_partials[(row_e + 1) * HID + h0]) =
            make_float4(hi[0], hi[1], hi[2], hi[3]);
    }
}

// ============================================================================
// Kernel 2: reduce partials over i, then bias+tanh and the two 64x64 layers.
// grid = 512 (one block per batch row), block = 64 threads (one per channel).
// ============================================================================
__global__ void mlp_epilogue_kernel(const float* __restrict__ b1,
                                    const float* __restrict__ W2,
                                    const float* __restrict__ b2,
                                    const float* __restrict__ W3,
                                    const float* __restrict__ b3,
                                    float* __restrict__ out)
{
    const int b = blockIdx.x;
    const int h = threadIdx.x;
    __shared__ float h1s[HID];
    __shared__ float h2s[HID];

    float acc = 0.0f;
    #pragma unroll 5
    for (int i = 0; i < DH; ++i)
        acc += g_partials[((size_t)i * BATCH + b) * HID + h];

    h1s[h] = tanhf(acc + b1[h]);
    __syncthreads();

    float acc2 = b2[h];
    #pragma unroll
    for (int jj = 0; jj < HID; ++jj)
        acc2 = fmaf(h1s[jj], W2[(size_t)jj * HID + h], acc2);
    h2s[h] = tanhf(acc2);
    __syncthreads();

    float acc3 = b3[h];
    #pragma unroll
    for (int jj = 0; jj < HID; ++jj)
        acc3 = fmaf(h2s[jj], W3[(size_t)jj * DL + h], acc3);
    out[(size_t)b * DL + h] = tanhf(acc3);
}

// ============================================================================
extern "C" void kernel_launch(void* const* d_in, const int* in_sizes, int n_in,
                              void* d_out, int out_size)
{
    const float* l  = (const float*)d_in[0];
    const float* a  = (const float*)d_in[1];
    const float* v  = (const float*)d_in[2];
    const float* W1 = (const float*)d_in[3];
    const float* b1 = (const float*)d_in[4];
    const float* W2 = (const float*)d_in[5];
    const float* b2 = (const float*)d_in[6];
    const float* W3 = (const float*)d_in[7];
    const float* b3 = (const float*)d_in[8];
    float* out = (float*)d_out;

    dim3 grid1(NMT, DH);   // x = mtile (adjacent CTAs share i -> L2 reuse of W1)
    fusion_gemm_kernel<<<grid1, THREADS>>>(l, a, v, W1);
    mlp_epilogue_kernel<<<BATCH, HID>>>(b1, W2, b2, W3, b3, out);
}

// round 8
// speedup vs baseline: 3.3917x; 3.3917x over previous
#include <cuda_runtime.h>
#include <cuda_fp16.h>
#include <cstdint>
#include <cstddef>

// ============================================================================
// out1[b,h] = sum_i a_h[b,i] * (G @ W1_i)[b,h],  G[b,jk] = v_h[b,j]*t_h[b,k]
// GEMM via mma.sync.m16n8k16 (f16 in, f32 accum) — compute_100-safe.
// CTA: 128 rows x (2 i-values => N=128 cols), K=4288 in 67 stages of 64.
// Partials[b][i][h] scaled by a_h at writeout; MLP epilogue reduces over i.
// ============================================================================

#define DL 64
#define DH 65
#define HID 64
#define BATCH 512
#define KREAL 4225          // 65*65 per i
#define KPAD 4288           // 67 chunks of 64
#define NC 67
#define STAGE_BYTES 32768   // A 16KB + B 16KB
#define GEMM_SMEM (2 * STAGE_BYTES)

__device__ __half g_G[(size_t)BATCH * KPAD];              // 4.4 MB
__device__ __half g_Bp[(size_t)DH * HID * KPAD];          // 35.7 MB  [i][h][k]
__device__ float  g_partials[(size_t)BATCH * DH * HID];   // 8.5 MB   [b][i][h]

// ---- helpers ---------------------------------------------------------------
static __device__ __forceinline__ uint32_t smem_u32(const void* p) {
    uint32_t a;
    asm("{ .reg .u64 t; cvta.to.shared.u64 t, %1; cvt.u32.u64 %0, t; }"
        : "=r"(a) : "l"(p));
    return a;
}
static __device__ __forceinline__ void cp16(uint32_t dst, const void* src) {
    asm volatile("cp.async.cg.shared.global [%0], [%1], 16;" :: "r"(dst), "l"(src));
}
#define CP_COMMIT() asm volatile("cp.async.commit_group;" ::: "memory")
#define CP_WAIT1()  asm volatile("cp.async.wait_group 1;" ::: "memory")

static __device__ __forceinline__ void ldm_x4(uint32_t* r, uint32_t addr) {
    asm volatile("ldmatrix.sync.aligned.m8n8.x4.shared.b16 {%0,%1,%2,%3}, [%4];"
                 : "=r"(r[0]), "=r"(r[1]), "=r"(r[2]), "=r"(r[3]) : "r"(addr));
}
static __device__ __forceinline__ void mma16816(float* c, const uint32_t* a,
                                                const uint32_t* b) {
    asm volatile(
        "mma.sync.aligned.m16n8k16.row.col.f32.f16.f16.f32 "
        "{%0,%1,%2,%3}, {%4,%5,%6,%7}, {%8,%9}, {%0,%1,%2,%3};"
        : "+f"(c[0]), "+f"(c[1]), "+f"(c[2]), "+f"(c[3])
        : "r"(a[0]), "r"(a[1]), "r"(a[2]), "r"(a[3]), "r"(b[0]), "r"(b[1]));
}

// ============================================================================
// Kernel A: convert+transpose W1 -> Bp[i][h][k] f16, zero-padded to KPAD.
// ============================================================================
__global__ void convert_w1_kernel(const float* __restrict__ W1) {
    __shared__ float ts[64][65];
    const int c = blockIdx.x, i = blockIdx.y;
    const int tid = threadIdx.x;
    for (int e = tid; e < 4096; e += 256) {
        int kl = e >> 6, h = e & 63;
        int jk = c * 64 + kl;
        ts[kl][h] = (jk < KREAL) ? W1[((size_t)i * KREAL + jk) * HID + h] : 0.0f;
    }
    __syncthreads();
    for (int t = tid; t < 512; t += 256) {
        int h = t >> 3, k16 = t & 7;
        uint32_t u[4];
        #pragma unroll
        for (int q = 0; q < 4; ++q) {
            __half2 p = __halves2half2(__float2half_rn(ts[k16 * 8 + 2 * q][h]),
                                       __float2half_rn(ts[k16 * 8 + 2 * q + 1][h]));
            u[q] = *reinterpret_cast<uint32_t*>(&p);
        }
        *reinterpret_cast<uint4*>(&g_Bp[((size_t)i * HID + h) * KPAD + c * 64 + k16 * 8])
            = make_uint4(u[0], u[1], u[2], u[3]);
    }
}

// ============================================================================
// Kernel B: build G[b][jk] = v_h[b,j]*t_h[b,k] f16, zero-padded. grid 512.
// ============================================================================
__global__ void build_g_kernel(const float* __restrict__ l,
                               const float* __restrict__ v) {
    const int b = blockIdx.x;
    const int tid = threadIdx.x;
    __shared__ float vs[DH], tsh[DH];
    if (tid < DH) vs[tid] = (tid == 0) ? 1.0f : v[(size_t)b * DL + tid - 1];
    if (tid >= 128 && tid < 128 + DH)
        tsh[tid - 128] = (tid == 128) ? 1.0f : l[(size_t)b * DL + tid - 129];
    __syncthreads();
    for (int p = tid; p < KPAD / 2; p += 256) {
        int jk0 = 2 * p, jk1 = 2 * p + 1;
        float f0 = (jk0 < KREAL) ? vs[jk0 / DH] * tsh[jk0 % DH] : 0.0f;
        float f1 = (jk1 < KREAL) ? vs[jk1 / DH] * tsh[jk1 % DH] : 0.0f;
        __half2 h2 = __halves2half2(__float2half_rn(f0), __float2half_rn(f1));
        *reinterpret_cast<uint32_t*>(&g_G[(size_t)b * KPAD + jk0])
            = *reinterpret_cast<uint32_t*>(&h2);
    }
}

// ============================================================================
// Kernel C: main GEMM via mma.sync. grid (4 mtiles, 33 i-pairs), 256 thr.
// smem/stage: A[128 rows][64 f16] swizzled (16KB) | B[128 n][64 f16] (16KB).
//   swizzle: 16B chunk index ch (0-7) stored at ch ^ (row & 7).
// Warps: 4 m-groups x 2 n-groups; warp tile 32m x 64n; acc 2x8 m16n8 frags.
// ============================================================================
__global__ void __launch_bounds__(256, 1)
fusion_mma_kernel(const float* __restrict__ a) {
    extern __shared__ char smc[];
    const uint32_t smb = smem_u32(smc);
    const int tid = threadIdx.x;
    const int lane = tid & 31;
    const int warp = tid >> 5;
    const int wm = warp & 3;          // 4 m-warps
    const int wn = warp >> 2;         // 2 n-warps
    const int mt = blockIdx.x, g = blockIdx.y;
    const int b0 = mt * 128;
    const int i0 = g * 2;

    auto issue_loads = [&](int c) {
        if (c >= NC) return;
        const uint32_t Ab = smb + (uint32_t)(c & 1) * STAGE_BYTES;
        const uint32_t Bb = Ab + 16384u;
        #pragma unroll
        for (int w = 0; w < 4; ++w) {                 // A: 128 rows x 8 chunks
            int idx = tid + w * 256;
            int row = idx >> 3, ch = idx & 7;
            cp16(Ab + (uint32_t)(row * 128 + ((ch ^ (row & 7)) << 4)),
                 &g_G[(size_t)(b0 + row) * KPAD + c * 64 + ch * 8]);
        }
        #pragma unroll
        for (int w = 0; w < 4; ++w) {                 // B: 128 n-rows x 8 chunks
            int idx = tid + w * 256;
            int n = idx >> 3, ch = idx & 7;
            int i = i0 + (n >> 6); if (i > DH - 1) i = DH - 1;
            int h = n & 63;
            cp16(Bb + (uint32_t)(n * 128 + ((ch ^ (n & 7)) << 4)),
                 &g_Bp[((size_t)i * HID + h) * KPAD + c * 64 + ch * 8]);
        }
    };

    float acc[2][8][4];
    #pragma unroll
    for (int mi = 0; mi < 2; ++mi)
        #pragma unroll
        for (int nj = 0; nj < 8; ++nj)
            #pragma unroll
            for (int q = 0; q < 4; ++q) acc[mi][nj][q] = 0.0f;

    issue_loads(0); CP_COMMIT();

    for (int c = 0; c < NC; ++c) {
        issue_loads(c + 1); CP_COMMIT();
        CP_WAIT1();                    // stage c resident
        __syncthreads();

        const uint32_t Ab = smb + (uint32_t)(c & 1) * STAGE_BYTES;
        const uint32_t Bb = Ab + 16384u;

        #pragma unroll
        for (int ks = 0; ks < 4; ++ks) {
            uint32_t af[2][4];
            #pragma unroll
            for (int mi = 0; mi < 2; ++mi) {
                int row = wm * 32 + mi * 16 + (lane & 15);
                int ch = 2 * ks + (lane >> 4);
                ldm_x4(af[mi], Ab + (uint32_t)(row * 128 + ((ch ^ (row & 7)) << 4)));
            }
            uint32_t bf[8][2];
            #pragma unroll
            for (int nb = 0; nb < 4; ++nb) {
                int nrow = wn * 64 + nb * 16 + (lane & 7) + ((lane >> 4) << 3);
                int ch = 2 * ks + ((lane >> 3) & 1);
                uint32_t r[4];
                ldm_x4(r, Bb + (uint32_t)(nrow * 128 + ((ch ^ (nrow & 7)) << 4)));
                bf[2 * nb][0] = r[0]; bf[2 * nb][1] = r[1];
                bf[2 * nb + 1][0] = r[2]; bf[2 * nb + 1][1] = r[3];
            }
            #pragma unroll
            for (int mi = 0; mi < 2; ++mi)
                #pragma unroll
                for (int nj = 0; nj < 8; ++nj)
                    mma16816(acc[mi][nj], af[mi], bf[nj]);
        }
        __syncthreads();               // done reading stage c before overwrite
    }

    // ---- writeout: scale by a_h[b, iw], iw uniform per warp ----
    const int iw = i0 + wn;
    if (iw < DH) {
        #pragma unroll
        for (int mi = 0; mi < 2; ++mi) {
            int bA = b0 + wm * 32 + mi * 16 + (lane >> 2);
            int bB = bA + 8;
            float ahA = (iw == 0) ? 1.0f : __ldg(&a[(size_t)bA * DL + iw - 1]);
            float ahB = (iw == 0) ? 1.0f : __ldg(&a[(size_t)bB * DL + iw - 1]);
            #pragma unroll
            for (int nj = 0; nj < 8; ++nj) {
                int h = nj * 8 + (lane & 3) * 2;
                float2 vA = make_float2(acc[mi][nj][0] * ahA, acc[mi][nj][1] * ahA);
                float2 vB = make_float2(acc[mi][nj][2] * ahB, acc[mi][nj][3] * ahB);
                *reinterpret_cast<float2*>(
                    &g_partials[((size_t)bA * DH + iw) * HID + h]) = vA;
                *reinterpret_cast<float2*>(
                    &g_partials[((size_t)bB * DH + iw) * HID + h]) = vB;
            }
        }
    }
}

// ============================================================================
// Kernel D: reduce over i + bias/tanh + two 64x64 layers. grid 128, 256 thr.
// ============================================================================
__global__ void mlp_epilogue_kernel(const float* __restrict__ b1,
                                    const float* __restrict__ W2,
                                    const float* __restrict__ b2,
                                    const float* __restrict__ W3,
                                    const float* __restrict__ b3,
                                    float* __restrict__ out) {
    const int tid = threadIdx.x;
    const int bl = tid >> 6;
    const int h = tid & 63;
    const int b = blockIdx.x * 4 + bl;
    __shared__ float h1s[4][HID];
    __shared__ float h2s[4][HID];

    const float* pr = &g_partials[(size_t)b * DH * HID + h];
    float acc = 0.0f;
    #pragma unroll 5
    for (int i = 0; i < DH; ++i) acc += pr[(size_t)i * HID];
    h1s[bl][h] = tanhf(acc + b1[h]);
    __syncthreads();

    float acc2 = b2[h];
    #pragma unroll
    for (int jj = 0; jj < HID; ++jj)
        acc2 = fmaf(h1s[bl][jj], W2[(size_t)jj * HID + h], acc2);
    h2s[bl][h] = tanhf(acc2);
    __syncthreads();

    float acc3 = b3[h];
    #pragma unroll
    for (int jj = 0; jj < HID; ++jj)
        acc3 = fmaf(h2s[bl][jj], W3[(size_t)jj * DL + h], acc3);
    out[(size_t)b * DL + h] = tanhf(acc3);
}

// ============================================================================
extern "C" void kernel_launch(void* const* d_in, const int* in_sizes, int n_in,
                              void* d_out, int out_size) {
    const float* l  = (const float*)d_in[0];
    const float* a  = (const float*)d_in[1];
    const float* v  = (const float*)d_in[2];
    const float* W1 = (const float*)d_in[3];
    const float* b1 = (const float*)d_in[4];
    const float* W2 = (const float*)d_in[5];
    const float* b2 = (const float*)d_in[6];
    const float* W3 = (const float*)d_in[7];
    const float* b3 = (const float*)d_in[8];
    float* out = (float*)d_out;

    cudaFuncSetAttribute(fusion_mma_kernel,
                         cudaFuncAttributeMaxDynamicSharedMemorySize, GEMM_SMEM);

    convert_w1_kernel<<<dim3(NC, DH), 256>>>(W1);
    build_g_kernel<<<BATCH, 256>>>(l, v);
    fusion_mma_kernel<<<dim3(4, 33), 256, GEMM_SMEM>>>(a);
    mlp_epilogue_kernel<<<128, 256>>>(b1, W2, b2, W3, b3, out);
}